// round 2
// baseline (speedup 1.0000x reference)
#include <cuda_runtime.h>
#include <cstdint>

#define NB 2
#define NH 16
#define NS 2048
#define ND 64

// Scratch (allocation-free rule: __device__ globals)
__device__ float g_Q[NB*NH*NS*ND];
__device__ float g_K[NB*NH*NS*ND];
__device__ float g_V[NB*NH*NS*ND];
__device__ unsigned g_keep[(size_t)NB*NH*NS*NS/32];   // 4M words = 16MB bitmask

// ---------------------------------------------------------------------------
// JAX threefry2x32, key = jax.random.key(42) -> (k0,k1) = (0,42)
// ---------------------------------------------------------------------------
__device__ __forceinline__ uint32_t rotl32(uint32_t x, int r) {
    return __funnelshift_l(x, x, r);
}

__device__ __forceinline__ void threefry2x32_42(uint32_t x0, uint32_t x1,
                                                uint32_t& o0, uint32_t& o1) {
    const uint32_t k0 = 0u, k1 = 42u, k2 = 0u ^ 42u ^ 0x1BD11BDAu;
    x0 += k0; x1 += k1;
#define TF_ROUND(r) { x0 += x1; x1 = rotl32(x1, (r)); x1 ^= x0; }
    TF_ROUND(13) TF_ROUND(15) TF_ROUND(26) TF_ROUND(6)
    x0 += k1; x1 += k2 + 1u;
    TF_ROUND(17) TF_ROUND(29) TF_ROUND(16) TF_ROUND(24)
    x0 += k2; x1 += k0 + 2u;
    TF_ROUND(13) TF_ROUND(15) TF_ROUND(26) TF_ROUND(6)
    x0 += k0; x1 += k1 + 3u;
    TF_ROUND(17) TF_ROUND(29) TF_ROUND(16) TF_ROUND(24)
    x0 += k1; x1 += k2 + 4u;
    TF_ROUND(13) TF_ROUND(15) TF_ROUND(26) TF_ROUND(6)
    x0 += k2; x1 += k0 + 5u;
#undef TF_ROUND
    o0 = x0; o1 = x1;
}

// keep  <=>  uniform < float32(0.9)  <=>  bits < 0xE6666600  (exact)
#define KEEP_THRESH 0xE6666600u

// JAX partitionable threefry (default since jax 0.4.36+):
//   bits[i] = out0 ^ out1 of threefry2x32(key, (hi32(i), lo32(i)))
// size = 2^27 < 2^32 so hi = 0.  Thread i packs keep-bits for elements
// [32i, 32i+32) into one word.  2^22 threads total.
__global__ void dropout_kernel() {
    uint32_t i = blockIdx.x * blockDim.x + threadIdx.x;   // [0, 2^22)
    uint32_t base = i << 5;
    uint32_t w = 0u;
#pragma unroll 8
    for (int j = 0; j < 32; j++) {
        uint32_t o0, o1;
        threefry2x32_42(0u, base + j, o0, o1);
        w |= ((o0 ^ o1) < KEEP_THRESH) ? (1u << j) : 0u;
    }
    g_keep[i] = w;
}

// ---------------------------------------------------------------------------
// QKV projection: Y[row,e] = sum_d X[row,d]*W[e,d] + b[e]
// rows = (b,s,h) flattened (65536), output written in [B,H,S,D] layout.
// 64x64 tile per block, 256 threads, 4x4 register tile per thread.
// Smem layouts are transposed [d][col] with xor-swizzle on float4 groups.
// ---------------------------------------------------------------------------
__global__ void proj_kernel(const float* __restrict__ X,
                            const float* __restrict__ W,
                            const float* __restrict__ bias, int which) {
    __shared__ __align__(16) float Xt[64][68];
    __shared__ __align__(16) float Wt[64][68];
    __shared__ float bs[64];
    float* Y = (which == 0) ? g_Q : (which == 1) ? g_K : g_V;

    int tid = threadIdx.x;
    if (tid < 64) bs[tid] = bias[tid];
    int r0 = blockIdx.x * 64;

#pragma unroll
    for (int r = 0; r < 4; r++) {
        int fidx = tid + r * 256;           // float4 index in 64x16 grid
        int row = fidx >> 4, dg = fidx & 15;
        int pg = (((row >> 2) ^ dg) << 2) + (row & 3);
        float4 w4 = reinterpret_cast<const float4*>(W)[fidx];   // W[e=row][4dg..]
        Wt[4*dg+0][pg] = w4.x; Wt[4*dg+1][pg] = w4.y;
        Wt[4*dg+2][pg] = w4.z; Wt[4*dg+3][pg] = w4.w;
        float4 x4 = reinterpret_cast<const float4*>(X + (size_t)(r0 + row) * 64)[dg];
        Xt[4*dg+0][pg] = x4.x; Xt[4*dg+1][pg] = x4.y;
        Xt[4*dg+2][pg] = x4.z; Xt[4*dg+3][pg] = x4.w;
    }
    __syncthreads();

    int ty = tid >> 4, tx = tid & 15;
    float acc[4][4] = {};
#pragma unroll 8
    for (int d = 0; d < 64; d++) {
        int sw = d >> 2;
        float4 xv = *reinterpret_cast<float4*>(&Xt[d][(ty ^ sw) << 2]);
        float4 wv = *reinterpret_cast<float4*>(&Wt[d][(tx ^ sw) << 2]);
        float xa[4] = {xv.x, xv.y, xv.z, xv.w};
        float wa[4] = {wv.x, wv.y, wv.z, wv.w};
#pragma unroll
        for (int i = 0; i < 4; i++)
#pragma unroll
            for (int j = 0; j < 4; j++) acc[i][j] += xa[i] * wa[j];
    }

#pragma unroll
    for (int i = 0; i < 4; i++) {
        int r = r0 + ty * 4 + i;            // global row = b*32768 + s*16 + h
        int b = r >> 15;
        int rem = r & 32767;
        int s = rem >> 4, h = rem & 15;
        float4 o;
        o.x = acc[i][0] + bs[tx*4+0];
        o.y = acc[i][1] + bs[tx*4+1];
        o.z = acc[i][2] + bs[tx*4+2];
        o.w = acc[i][3] + bs[tx*4+3];
        reinterpret_cast<float4*>(Y + ((size_t)(b*NH + h)*NS + s)*ND)[tx] = o;
    }
}

// ---------------------------------------------------------------------------
// Flash attention with exact-JAX dropout.
// Block: (qtile=64 queries) x (head) x (batch). 256 threads (16x16).
// Online softmax; dropout applied inside PV accumulation; out = acc/(l*0.9).
// ---------------------------------------------------------------------------
__global__ void attn_kernel(const float* __restrict__ mask,
                            float* __restrict__ out) {
    extern __shared__ __align__(16) float sm[];
    float (*Qt)[68]  = reinterpret_cast<float(*)[68]>(sm);            // [d][q]
    float (*Kt)[68]  = reinterpret_cast<float(*)[68]>(sm + 4352);     // [d][k]
    float (*Vs)[68]  = reinterpret_cast<float(*)[68]>(sm + 2*4352);   // [k][d]
    float (*Pst)[68] = reinterpret_cast<float(*)[68]>(sm + 3*4352);   // [k][q]

    int tid = threadIdx.x;
    int ty = tid >> 4, tx = tid & 15;
    int qt = blockIdx.x, h = blockIdx.y, b = blockIdx.z;
    int bh = b * NH + h;

    // Load Q tile transposed, pre-scaled by 1/sqrt(D)=1/8
    const float* Qg = g_Q + ((size_t)bh * NS + qt * 64) * ND;
#pragma unroll
    for (int r = 0; r < 4; r++) {
        int fidx = tid + r * 256;
        int row = fidx >> 4, dg = fidx & 15;
        int pg = (((row >> 2) ^ dg) << 2) + (row & 3);
        float4 q4 = reinterpret_cast<const float4*>(Qg + row * ND)[dg];
        Qt[4*dg+0][pg] = q4.x * 0.125f; Qt[4*dg+1][pg] = q4.y * 0.125f;
        Qt[4*dg+2][pg] = q4.z * 0.125f; Qt[4*dg+3][pg] = q4.w * 0.125f;
    }

    float m[4], l[4], acc[4][4];
#pragma unroll
    for (int i = 0; i < 4; i++) {
        m[i] = -3.0e38f; l[i] = 0.f;
#pragma unroll
        for (int j = 0; j < 4; j++) acc[i][j] = 0.f;
    }

    const float* maskBase = mask + ((size_t)b * NS + qt * 64) * NS;
    uint32_t kwbase = ((uint32_t)bh * NS + (uint32_t)qt * 64) * (NS / 32);

    for (int kt = 0; kt < 32; kt++) {
        __syncthreads();   // protect Kt/Vs/Pst reuse
        const float* Kg = g_K + ((size_t)bh * NS + kt * 64) * ND;
        const float* Vg = g_V + ((size_t)bh * NS + kt * 64) * ND;
#pragma unroll
        for (int r = 0; r < 4; r++) {
            int fidx = tid + r * 256;
            int row = fidx >> 4, dg = fidx & 15;
            int pg = (((row >> 2) ^ dg) << 2) + (row & 3);
            float4 k4 = reinterpret_cast<const float4*>(Kg + row * ND)[dg];
            Kt[4*dg+0][pg] = k4.x; Kt[4*dg+1][pg] = k4.y;
            Kt[4*dg+2][pg] = k4.z; Kt[4*dg+3][pg] = k4.w;
            float4 v4 = reinterpret_cast<const float4*>(Vg + row * ND)[dg];
            *reinterpret_cast<float4*>(&Vs[row][(dg ^ (row & 15)) << 2]) = v4;
        }
        __syncthreads();

        // --- scores: s = (Q/8) . K ---
        float s[4][4] = {};
#pragma unroll 8
        for (int d = 0; d < 64; d++) {
            int sw = d >> 2;
            float4 qv = *reinterpret_cast<float4*>(&Qt[d][(ty ^ sw) << 2]);
            float4 kv = *reinterpret_cast<float4*>(&Kt[d][(tx ^ sw) << 2]);
            float qa[4] = {qv.x, qv.y, qv.z, qv.w};
            float ka[4] = {kv.x, kv.y, kv.z, kv.w};
#pragma unroll
            for (int i = 0; i < 4; i++)
#pragma unroll
                for (int j = 0; j < 4; j++) s[i][j] += qa[i] * ka[j];
        }

        // --- mask + online softmax + dropout -> Pst ---
#pragma unroll
        for (int i = 0; i < 4; i++) {
            const float* mrow = maskBase + (size_t)(ty*4 + i) * NS + kt*64 + tx*4;
            float4 mk = *reinterpret_cast<const float4*>(mrow);
            s[i][0] += mk.x; s[i][1] += mk.y; s[i][2] += mk.z; s[i][3] += mk.w;

            float rm = fmaxf(fmaxf(s[i][0], s[i][1]), fmaxf(s[i][2], s[i][3]));
#pragma unroll
            for (int o = 1; o < 16; o <<= 1)
                rm = fmaxf(rm, __shfl_xor_sync(0xffffffffu, rm, o));
            float mn = fmaxf(m[i], rm);

            float p0 = __expf(s[i][0] - mn);
            float p1 = __expf(s[i][1] - mn);
            float p2 = __expf(s[i][2] - mn);
            float p3 = __expf(s[i][3] - mn);
            float ps = (p0 + p1) + (p2 + p3);
#pragma unroll
            for (int o = 1; o < 16; o <<= 1)
                ps += __shfl_xor_sync(0xffffffffu, ps, o);

            float sc = __expf(m[i] - mn);
            m[i] = mn;
            l[i] = l[i] * sc + ps;
            acc[i][0] *= sc; acc[i][1] *= sc; acc[i][2] *= sc; acc[i][3] *= sc;

            uint32_t w = g_keep[kwbase + (uint32_t)(ty*4 + i) * 64
                                + (uint32_t)kt * 2 + (tx >> 3)];
            int b0 = (tx & 7) * 4;
            int pc = ((ty ^ tx) << 2) + i;
            Pst[4*tx+0][pc] = ((w >> (b0 + 0)) & 1u) ? p0 : 0.f;
            Pst[4*tx+1][pc] = ((w >> (b0 + 1)) & 1u) ? p1 : 0.f;
            Pst[4*tx+2][pc] = ((w >> (b0 + 2)) & 1u) ? p2 : 0.f;
            Pst[4*tx+3][pc] = ((w >> (b0 + 3)) & 1u) ? p3 : 0.f;
        }
        __syncthreads();

        // --- PV: acc += P . V ---
#pragma unroll 8
        for (int k = 0; k < 64; k++) {
            int sw = k >> 2;
            float4 pv = *reinterpret_cast<float4*>(&Pst[k][(ty ^ sw) << 2]);
            float4 vv = *reinterpret_cast<float4*>(&Vs[k][(tx ^ (k & 15)) << 2]);
            float pa[4] = {pv.x, pv.y, pv.z, pv.w};
            float va[4] = {vv.x, vv.y, vv.z, vv.w};
#pragma unroll
            for (int i = 0; i < 4; i++)
#pragma unroll
                for (int j = 0; j < 4; j++) acc[i][j] += pa[i] * va[j];
        }
    }

    // epilogue: out = acc / (l * 0.9)
#pragma unroll
    for (int i = 0; i < 4; i++) {
        float inv = 1.0f / (l[i] * 0.9f);
        float4 o;
        o.x = acc[i][0] * inv; o.y = acc[i][1] * inv;
        o.z = acc[i][2] * inv; o.w = acc[i][3] * inv;
        reinterpret_cast<float4*>(
            out + ((size_t)bh * NS + qt * 64 + ty * 4 + i) * ND)[tx] = o;
    }
}

// ---------------------------------------------------------------------------
extern "C" void kernel_launch(void* const* d_in, const int* in_sizes, int n_in,
                              void* d_out, int out_size) {
    (void)in_sizes; (void)n_in; (void)out_size;
    const float* q   = (const float*)d_in[0];
    const float* k   = (const float*)d_in[1];
    const float* v   = (const float*)d_in[2];
    const float* msk = (const float*)d_in[3];
    const float* Wq  = (const float*)d_in[4];
    const float* bq  = (const float*)d_in[5];
    const float* Wk  = (const float*)d_in[6];
    const float* bk  = (const float*)d_in[7];
    const float* Wv  = (const float*)d_in[8];
    const float* bv  = (const float*)d_in[9];
    float* out = (float*)d_out;

    const int smem_bytes = 4 * 4352 * 4;   // 69632 B
    cudaFuncSetAttribute(attn_kernel,
                         cudaFuncAttributeMaxDynamicSharedMemorySize, smem_bytes);

    dropout_kernel<<<16384, 256>>>();
    proj_kernel<<<1024, 256>>>(q, Wq, bq, 0);
    proj_kernel<<<1024, 256>>>(k, Wk, bk, 1);
    proj_kernel<<<1024, 256>>>(v, Wv, bv, 2);

    dim3 grid(NS / 64, NH, NB);
    attn_kernel<<<grid, 256, smem_bytes>>>(msk, out);
}

// round 4
// speedup vs baseline: 1.4762x; 1.4762x over previous
#include <cuda_runtime.h>
#include <cstdint>

#define NB 2
#define NH 16
#define NS 2048
#define ND 64

// Scratch (allocation-free rule: __device__ globals)
__device__ float g_Q[NB*NH*NS*ND];
__device__ float g_K[NB*NH*NS*ND];
__device__ float g_V[NB*NH*NS*ND];
__device__ unsigned g_keep[(size_t)NB*NH*NS*NS/32];   // 16MB keep bitmask

// ---------------------------------------------------------------------------
// helpers
// ---------------------------------------------------------------------------
__device__ __forceinline__ uint32_t f2tf32(float x) {
    uint32_t r;
    asm("cvt.rna.tf32.f32 %0, %1;" : "=r"(r) : "f"(x));
    return r;
}
__device__ __forceinline__ uint4 tf4(float4 v) {
    return make_uint4(f2tf32(v.x), f2tf32(v.y), f2tf32(v.z), f2tf32(v.w));
}
// m16n8k8 tf32 warp MMA, fp32 accumulate (base ISA, works on sm_103 target)
__device__ __forceinline__ void mma8(float* c, const uint32_t* a,
                                     uint32_t b0, uint32_t b1) {
    asm volatile(
        "mma.sync.aligned.m16n8k8.row.col.f32.tf32.tf32.f32 "
        "{%0,%1,%2,%3}, {%4,%5,%6,%7}, {%8,%9}, {%0,%1,%2,%3};"
        : "+f"(c[0]), "+f"(c[1]), "+f"(c[2]), "+f"(c[3])
        : "r"(a[0]), "r"(a[1]), "r"(a[2]), "r"(a[3]), "r"(b0), "r"(b1));
}

// ---------------------------------------------------------------------------
// JAX partitionable threefry2x32, key=(0,42): bits[i] = o0^o1, counter (0,i)
// ---------------------------------------------------------------------------
__device__ __forceinline__ uint32_t rotl32(uint32_t x, int r) {
    return __funnelshift_l(x, x, r);
}
__device__ __forceinline__ void threefry2x32_42(uint32_t x0, uint32_t x1,
                                                uint32_t& o0, uint32_t& o1) {
    const uint32_t k0 = 0u, k1 = 42u, k2 = 0u ^ 42u ^ 0x1BD11BDAu;
    x0 += k0; x1 += k1;
#define TF_ROUND(r) { x0 += x1; x1 = rotl32(x1, (r)); x1 ^= x0; }
    TF_ROUND(13) TF_ROUND(15) TF_ROUND(26) TF_ROUND(6)
    x0 += k1; x1 += k2 + 1u;
    TF_ROUND(17) TF_ROUND(29) TF_ROUND(16) TF_ROUND(24)
    x0 += k2; x1 += k0 + 2u;
    TF_ROUND(13) TF_ROUND(15) TF_ROUND(26) TF_ROUND(6)
    x0 += k0; x1 += k1 + 3u;
    TF_ROUND(17) TF_ROUND(29) TF_ROUND(16) TF_ROUND(24)
    x0 += k1; x1 += k2 + 4u;
    TF_ROUND(13) TF_ROUND(15) TF_ROUND(26) TF_ROUND(6)
    x0 += k2; x1 += k0 + 5u;
#undef TF_ROUND
    o0 = x0; o1 = x1;
}
#define KEEP_THRESH 0xE6666600u   // uniform < 0.9f, exact integer reduction

__global__ void dropout_kernel() {
    uint32_t i = blockIdx.x * blockDim.x + threadIdx.x;   // [0, 2^22)
    uint32_t base = i << 5;
    uint32_t w = 0u;
#pragma unroll 8
    for (int j = 0; j < 32; j++) {
        uint32_t o0, o1;
        threefry2x32_42(0u, base + j, o0, o1);
        w |= ((o0 ^ o1) < KEEP_THRESH) ? (1u << j) : 0u;
    }
    g_keep[i] = w;
}

// ---------------------------------------------------------------------------
// QKV projection (validated in R2): Y = X @ W^T + b, output [B,H,S,D]
// ---------------------------------------------------------------------------
__global__ void proj_kernel(const float* __restrict__ X,
                            const float* __restrict__ W,
                            const float* __restrict__ bias, int which) {
    __shared__ __align__(16) float Xt[64][68];
    __shared__ __align__(16) float Wt[64][68];
    __shared__ float bs[64];
    float* Y = (which == 0) ? g_Q : (which == 1) ? g_K : g_V;

    int tid = threadIdx.x;
    if (tid < 64) bs[tid] = bias[tid];
    int r0 = blockIdx.x * 64;

#pragma unroll
    for (int r = 0; r < 4; r++) {
        int fidx = tid + r * 256;
        int row = fidx >> 4, dg = fidx & 15;
        int pg = (((row >> 2) ^ dg) << 2) + (row & 3);
        float4 w4 = reinterpret_cast<const float4*>(W)[fidx];
        Wt[4*dg+0][pg] = w4.x; Wt[4*dg+1][pg] = w4.y;
        Wt[4*dg+2][pg] = w4.z; Wt[4*dg+3][pg] = w4.w;
        float4 x4 = reinterpret_cast<const float4*>(X + (size_t)(r0 + row) * 64)[dg];
        Xt[4*dg+0][pg] = x4.x; Xt[4*dg+1][pg] = x4.y;
        Xt[4*dg+2][pg] = x4.z; Xt[4*dg+3][pg] = x4.w;
    }
    __syncthreads();

    int ty = tid >> 4, tx = tid & 15;
    float acc[4][4] = {};
#pragma unroll 8
    for (int d = 0; d < 64; d++) {
        int sw = d >> 2;
        float4 xv = *reinterpret_cast<float4*>(&Xt[d][(ty ^ sw) << 2]);
        float4 wv = *reinterpret_cast<float4*>(&Wt[d][(tx ^ sw) << 2]);
        float xa[4] = {xv.x, xv.y, xv.z, xv.w};
        float wa[4] = {wv.x, wv.y, wv.z, wv.w};
#pragma unroll
        for (int i = 0; i < 4; i++)
#pragma unroll
            for (int j = 0; j < 4; j++) acc[i][j] += xa[i] * wa[j];
    }

#pragma unroll
    for (int i = 0; i < 4; i++) {
        int r = r0 + ty * 4 + i;
        int b = r >> 15;
        int rem = r & 32767;
        int s = rem >> 4, h = rem & 15;
        float4 o;
        o.x = acc[i][0] + bs[tx*4+0];
        o.y = acc[i][1] + bs[tx*4+1];
        o.z = acc[i][2] + bs[tx*4+2];
        o.w = acc[i][3] + bs[tx*4+3];
        reinterpret_cast<float4*>(Y + ((size_t)(b*NH + h)*NS + s)*ND)[tx] = o;
    }
}

// ---------------------------------------------------------------------------
// Warp-MMA (m16n8k8 tf32) flash attention.
// Block: 128 queries x head x batch, 256 threads = 8 warps (16 q-rows each).
// SMEM (uint32 words): Ks [64][68], Vs [64][72], Ps [8 warps][16][68]
//                      (Ps region doubles as Q staging before the mainloop).
// ---------------------------------------------------------------------------
#define KS_OFF 0
#define VS_OFF 4352          /* 64*68 */
#define PS_OFF 8960          /* + 64*72 */
#define SMEM_WORDS 17664     /* + 8*16*68 */

__global__ __launch_bounds__(256) void attn_mma_kernel(
        const float* __restrict__ mask, float* __restrict__ out) {
    extern __shared__ __align__(16) uint32_t sm[];
    uint32_t* Ks = sm + KS_OFF;
    uint32_t* Vs = sm + VS_OFF;
    uint32_t* Ps = sm + PS_OFF;

    int tid = threadIdx.x;
    int lane = tid & 31, w = tid >> 5;
    int gi = lane >> 2, ci = lane & 3;
    int qt = blockIdx.x, h = blockIdx.y, b = blockIdx.z;
    int bh = b * NH + h;
    int q0 = qt * 128;

    // ---- stage Q (scaled 1/8, tf32) into Ps region, then build A-fragments
    {
        int row = tid >> 1, hf = tid & 1;
        const float4* Qg = reinterpret_cast<const float4*>(
            g_Q + ((size_t)bh * NS + q0 + row) * ND);
        uint32_t* dst = Ps + row * 68;
#pragma unroll
        for (int j = 0; j < 8; j++) {
            float4 v = Qg[hf * 8 + j];
            v.x *= 0.125f; v.y *= 0.125f; v.z *= 0.125f; v.w *= 0.125f;
            *reinterpret_cast<uint4*>(dst + (hf * 8 + j) * 4) = tf4(v);
        }
    }
    __syncthreads();
    uint32_t qf[8][4];
    {
        const uint32_t* Qs = Ps + (w * 16) * 68;
#pragma unroll
        for (int kc = 0; kc < 8; kc++) {
            qf[kc][0] = Qs[gi * 68 + kc * 8 + ci];
            qf[kc][1] = Qs[(gi + 8) * 68 + kc * 8 + ci];
            qf[kc][2] = Qs[gi * 68 + kc * 8 + ci + 4];
            qf[kc][3] = Qs[(gi + 8) * 68 + kc * 8 + ci + 4];
        }
    }

    float oacc[8][4] = {};
    float m_lo = -3.0e38f, m_hi = -3.0e38f, l_lo = 0.f, l_hi = 0.f;

    int rlo = q0 + w * 16 + gi, rhi = rlo + 8;
    const float* mask_lo = mask + ((size_t)b * NS + rlo) * NS;
    const float* mask_hi = mask + ((size_t)b * NS + rhi) * NS;
    const unsigned* kw_lo = g_keep + (size_t)(bh * NS + rlo) * (NS / 32);
    const unsigned* kw_hi = g_keep + (size_t)(bh * NS + rhi) * (NS / 32);

    // GMEM prefetch of tile 0 into registers
    int prow = tid >> 2, pg = tid & 3;
    const float* Kbase = g_K + ((size_t)bh * NS + prow) * ND;
    const float* Vbase = g_V + ((size_t)bh * NS + prow) * ND;
    float4 kreg[4], vreg[4];
#pragma unroll
    for (int j = 0; j < 4; j++) {
        kreg[j] = reinterpret_cast<const float4*>(Kbase)[pg * 4 + j];
        vreg[j] = reinterpret_cast<const float4*>(Vbase)[pg * 4 + j];
    }

    for (int kt = 0; kt < 32; kt++) {
        // commit prefetched tile to smem (tf32)
#pragma unroll
        for (int j = 0; j < 4; j++) {
            int col = (pg * 4 + j) * 4;
            *reinterpret_cast<uint4*>(Ks + prow * 68 + col) = tf4(kreg[j]);
            *reinterpret_cast<uint4*>(Vs + prow * 72 + col) = tf4(vreg[j]);
        }
        __syncthreads();
        if (kt + 1 < 32) {
            const float* Kn = Kbase + (size_t)(kt + 1) * 64 * ND;
            const float* Vn = Vbase + (size_t)(kt + 1) * 64 * ND;
#pragma unroll
            for (int j = 0; j < 4; j++) {
                kreg[j] = reinterpret_cast<const float4*>(Kn)[pg * 4 + j];
                vreg[j] = reinterpret_cast<const float4*>(Vn)[pg * 4 + j];
            }
        }

        // ---- S = Q @ K^T ----
        float s[8][4] = {};
#pragma unroll
        for (int kc = 0; kc < 8; kc++) {
#pragma unroll
            for (int nt = 0; nt < 8; nt++) {
                uint32_t b0 = Ks[(nt * 8 + gi) * 68 + kc * 8 + ci];
                uint32_t b1 = Ks[(nt * 8 + gi) * 68 + kc * 8 + ci + 4];
                mma8(s[nt], qf[kc], b0, b1);
            }
        }

        // ---- mask + online softmax ----
        float mxl = -3.0e38f, mxh = -3.0e38f;
#pragma unroll
        for (int nt = 0; nt < 8; nt++) {
            float2 ml = *reinterpret_cast<const float2*>(
                mask_lo + kt * 64 + nt * 8 + 2 * ci);
            float2 mh = *reinterpret_cast<const float2*>(
                mask_hi + kt * 64 + nt * 8 + 2 * ci);
            s[nt][0] += ml.x; s[nt][1] += ml.y;
            s[nt][2] += mh.x; s[nt][3] += mh.y;
            mxl = fmaxf(mxl, fmaxf(s[nt][0], s[nt][1]));
            mxh = fmaxf(mxh, fmaxf(s[nt][2], s[nt][3]));
        }
        mxl = fmaxf(mxl, __shfl_xor_sync(0xffffffffu, mxl, 1));
        mxl = fmaxf(mxl, __shfl_xor_sync(0xffffffffu, mxl, 2));
        mxh = fmaxf(mxh, __shfl_xor_sync(0xffffffffu, mxh, 1));
        mxh = fmaxf(mxh, __shfl_xor_sync(0xffffffffu, mxh, 2));

        float nml = fmaxf(m_lo, mxl), nmh = fmaxf(m_hi, mxh);
        float scl = __expf(m_lo - nml), sch = __expf(m_hi - nmh);
        m_lo = nml; m_hi = nmh;

        float suml = 0.f, sumh = 0.f;
#pragma unroll
        for (int nt = 0; nt < 8; nt++) {
            s[nt][0] = __expf(s[nt][0] - nml);
            s[nt][1] = __expf(s[nt][1] - nml);
            s[nt][2] = __expf(s[nt][2] - nmh);
            s[nt][3] = __expf(s[nt][3] - nmh);
            suml += s[nt][0] + s[nt][1];
            sumh += s[nt][2] + s[nt][3];
        }
        suml += __shfl_xor_sync(0xffffffffu, suml, 1);
        suml += __shfl_xor_sync(0xffffffffu, suml, 2);
        sumh += __shfl_xor_sync(0xffffffffu, sumh, 1);
        sumh += __shfl_xor_sync(0xffffffffu, sumh, 2);
        l_lo = l_lo * scl + suml;
        l_hi = l_hi * sch + sumh;
#pragma unroll
        for (int nt = 0; nt < 8; nt++) {
            oacc[nt][0] *= scl; oacc[nt][1] *= scl;
            oacc[nt][2] *= sch; oacc[nt][3] *= sch;
        }

        // ---- dropout + P store (per-warp private region) ----
        uint2 klo = *reinterpret_cast<const uint2*>(kw_lo + kt * 2);
        uint2 khi = *reinterpret_cast<const uint2*>(kw_hi + kt * 2);
        uint32_t* Pw = Ps + w * 16 * 68;
#pragma unroll
        for (int nt = 0; nt < 8; nt++) {
            int c0 = nt * 8 + 2 * ci;
            uint32_t wl = (c0 < 32) ? klo.x : klo.y;
            uint32_t wh = (c0 < 32) ? khi.x : khi.y;
            int bit = c0 & 31;
            uint2 plo, phi;
            plo.x = ((wl >> bit) & 1u)       ? f2tf32(s[nt][0]) : 0u;
            plo.y = ((wl >> (bit + 1)) & 1u) ? f2tf32(s[nt][1]) : 0u;
            phi.x = ((wh >> bit) & 1u)       ? f2tf32(s[nt][2]) : 0u;
            phi.y = ((wh >> (bit + 1)) & 1u) ? f2tf32(s[nt][3]) : 0u;
            *reinterpret_cast<uint2*>(Pw + gi * 68 + c0) = plo;
            *reinterpret_cast<uint2*>(Pw + (gi + 8) * 68 + c0) = phi;
        }
        __syncwarp();

        // ---- O += P @ V ----
#pragma unroll
        for (int kc = 0; kc < 8; kc++) {
            uint32_t a[4];
            a[0] = Pw[gi * 68 + kc * 8 + ci];
            a[1] = Pw[(gi + 8) * 68 + kc * 8 + ci];
            a[2] = Pw[gi * 68 + kc * 8 + ci + 4];
            a[3] = Pw[(gi + 8) * 68 + kc * 8 + ci + 4];
#pragma unroll
            for (int nt = 0; nt < 8; nt++) {
                uint32_t b0 = Vs[(kc * 8 + ci) * 72 + nt * 8 + gi];
                uint32_t b1 = Vs[(kc * 8 + ci + 4) * 72 + nt * 8 + gi];
                mma8(oacc[nt], a, b0, b1);
            }
        }
        __syncthreads();
    }

    // epilogue: out = oacc / (l * 0.9)
    float invl = 1.0f / (l_lo * 0.9f);
    float invh = 1.0f / (l_hi * 0.9f);
    float* out_lo = out + ((size_t)bh * NS + rlo) * ND;
    float* out_hi = out + ((size_t)bh * NS + rhi) * ND;
#pragma unroll
    for (int nt = 0; nt < 8; nt++) {
        float2 a, c;
        a.x = oacc[nt][0] * invl; a.y = oacc[nt][1] * invl;
        c.x = oacc[nt][2] * invh; c.y = oacc[nt][3] * invh;
        *reinterpret_cast<float2*>(out_lo + nt * 8 + 2 * ci) = a;
        *reinterpret_cast<float2*>(out_hi + nt * 8 + 2 * ci) = c;
    }
}

// ---------------------------------------------------------------------------
extern "C" void kernel_launch(void* const* d_in, const int* in_sizes, int n_in,
                              void* d_out, int out_size) {
    (void)in_sizes; (void)n_in; (void)out_size;
    const float* q   = (const float*)d_in[0];
    const float* k   = (const float*)d_in[1];
    const float* v   = (const float*)d_in[2];
    const float* msk = (const float*)d_in[3];
    const float* Wq  = (const float*)d_in[4];
    const float* bq  = (const float*)d_in[5];
    const float* Wk  = (const float*)d_in[6];
    const float* bk  = (const float*)d_in[7];
    const float* Wv  = (const float*)d_in[8];
    const float* bv  = (const float*)d_in[9];
    float* out = (float*)d_out;

    const int smem_bytes = SMEM_WORDS * 4;   // 70656 B
    cudaFuncSetAttribute(attn_mma_kernel,
                         cudaFuncAttributeMaxDynamicSharedMemorySize, smem_bytes);

    dropout_kernel<<<16384, 256>>>();
    proj_kernel<<<1024, 256>>>(q, Wq, bq, 0);
    proj_kernel<<<1024, 256>>>(k, Wk, bk, 1);
    proj_kernel<<<1024, 256>>>(v, Wv, bv, 2);

    dim3 grid(NS / 128, NH, NB);
    attn_mma_kernel<<<grid, 256, smem_bytes>>>(msk, out);
}

// round 5
// speedup vs baseline: 1.5945x; 1.0802x over previous
#include <cuda_runtime.h>
#include <cstdint>

#define NB 2
#define NH 16
#define NS 2048
#define ND 64

// Scratch (allocation-free rule: __device__ globals)
__device__ float g_Q[NB*NH*NS*ND];
__device__ float g_K[NB*NH*NS*ND];
__device__ float g_V[NB*NH*NS*ND];

// ---------------------------------------------------------------------------
// helpers
// ---------------------------------------------------------------------------
__device__ __forceinline__ uint32_t f2tf32(float x) {
    uint32_t r;
    asm("cvt.rna.tf32.f32 %0, %1;" : "=r"(r) : "f"(x));
    return r;
}
__device__ __forceinline__ uint4 tf4(float4 v) {
    return make_uint4(f2tf32(v.x), f2tf32(v.y), f2tf32(v.z), f2tf32(v.w));
}
// m16n8k8 tf32 warp MMA, fp32 accumulate (base ISA, works on sm_103 target)
__device__ __forceinline__ void mma8(float* c, const uint32_t* a,
                                     uint32_t b0, uint32_t b1) {
    asm volatile(
        "mma.sync.aligned.m16n8k8.row.col.f32.tf32.tf32.f32 "
        "{%0,%1,%2,%3}, {%4,%5,%6,%7}, {%8,%9}, {%0,%1,%2,%3};"
        : "+f"(c[0]), "+f"(c[1]), "+f"(c[2]), "+f"(c[3])
        : "r"(a[0]), "r"(a[1]), "r"(a[2]), "r"(a[3]), "r"(b0), "r"(b1));
}

// ---------------------------------------------------------------------------
// JAX partitionable threefry2x32, key=(0,42): bits[i] = o0^o1, counter (0,i)
// ---------------------------------------------------------------------------
__device__ __forceinline__ uint32_t rotl32(uint32_t x, int r) {
    return __funnelshift_l(x, x, r);
}
__device__ __forceinline__ void threefry2x32_42(uint32_t x0, uint32_t x1,
                                                uint32_t& o0, uint32_t& o1) {
    const uint32_t k0 = 0u, k1 = 42u, k2 = 0u ^ 42u ^ 0x1BD11BDAu;
    x0 += k0; x1 += k1;
#define TF_ROUND(r) { x0 += x1; x1 = rotl32(x1, (r)); x1 ^= x0; }
    TF_ROUND(13) TF_ROUND(15) TF_ROUND(26) TF_ROUND(6)
    x0 += k1; x1 += k2 + 1u;
    TF_ROUND(17) TF_ROUND(29) TF_ROUND(16) TF_ROUND(24)
    x0 += k2; x1 += k0 + 2u;
    TF_ROUND(13) TF_ROUND(15) TF_ROUND(26) TF_ROUND(6)
    x0 += k0; x1 += k1 + 3u;
    TF_ROUND(17) TF_ROUND(29) TF_ROUND(16) TF_ROUND(24)
    x0 += k1; x1 += k2 + 4u;
    TF_ROUND(13) TF_ROUND(15) TF_ROUND(26) TF_ROUND(6)
    x0 += k2; x1 += k0 + 5u;
#undef TF_ROUND
    o0 = x0; o1 = x1;
}
#define KEEP_THRESH 0xE6666600u   // uniform < 0.9f, exact integer reduction

__device__ __forceinline__ uint32_t keep1(uint32_t e) {
    uint32_t o0, o1;
    threefry2x32_42(0u, e, o0, o1);
    return ((o0 ^ o1) < KEEP_THRESH) ? 1u : 0u;
}

// ---------------------------------------------------------------------------
// QKV projection (validated in R2): Y = X @ W^T + b, output [B,H,S,D]
// ---------------------------------------------------------------------------
__global__ void proj_kernel(const float* __restrict__ X,
                            const float* __restrict__ W,
                            const float* __restrict__ bias, int which) {
    __shared__ __align__(16) float Xt[64][68];
    __shared__ __align__(16) float Wt[64][68];
    __shared__ float bs[64];
    float* Y = (which == 0) ? g_Q : (which == 1) ? g_K : g_V;

    int tid = threadIdx.x;
    if (tid < 64) bs[tid] = bias[tid];
    int r0 = blockIdx.x * 64;

#pragma unroll
    for (int r = 0; r < 4; r++) {
        int fidx = tid + r * 256;
        int row = fidx >> 4, dg = fidx & 15;
        int pg = (((row >> 2) ^ dg) << 2) + (row & 3);
        float4 w4 = reinterpret_cast<const float4*>(W)[fidx];
        Wt[4*dg+0][pg] = w4.x; Wt[4*dg+1][pg] = w4.y;
        Wt[4*dg+2][pg] = w4.z; Wt[4*dg+3][pg] = w4.w;
        float4 x4 = reinterpret_cast<const float4*>(X + (size_t)(r0 + row) * 64)[dg];
        Xt[4*dg+0][pg] = x4.x; Xt[4*dg+1][pg] = x4.y;
        Xt[4*dg+2][pg] = x4.z; Xt[4*dg+3][pg] = x4.w;
    }
    __syncthreads();

    int ty = tid >> 4, tx = tid & 15;
    float acc[4][4] = {};
#pragma unroll 8
    for (int d = 0; d < 64; d++) {
        int sw = d >> 2;
        float4 xv = *reinterpret_cast<float4*>(&Xt[d][(ty ^ sw) << 2]);
        float4 wv = *reinterpret_cast<float4*>(&Wt[d][(tx ^ sw) << 2]);
        float xa[4] = {xv.x, xv.y, xv.z, xv.w};
        float wa[4] = {wv.x, wv.y, wv.z, wv.w};
#pragma unroll
        for (int i = 0; i < 4; i++)
#pragma unroll
            for (int j = 0; j < 4; j++) acc[i][j] += xa[i] * wa[j];
    }

#pragma unroll
    for (int i = 0; i < 4; i++) {
        int r = r0 + ty * 4 + i;
        int b = r >> 15;
        int rem = r & 32767;
        int s = rem >> 4, h = rem & 15;
        float4 o;
        o.x = acc[i][0] + bs[tx*4+0];
        o.y = acc[i][1] + bs[tx*4+1];
        o.z = acc[i][2] + bs[tx*4+2];
        o.w = acc[i][3] + bs[tx*4+3];
        reinterpret_cast<float4*>(Y + ((size_t)(b*NH + h)*NS + s)*ND)[tx] = o;
    }
}

// ---------------------------------------------------------------------------
// Warp-MMA (m16n8k8 tf32) flash attention with FUSED threefry dropout.
// Block: 64 queries x head x batch, 128 threads = 4 warps (16 q-rows each).
// SMEM (uint32): Ks [64][68], Vs [64][72], Ps [4 warps][16][68]
//                (Ps doubles as Q staging before the mainloop).
// 3 blocks/SM (53KB smem, <=170 regs) -> 12 warps/SM for latency hiding.
// ---------------------------------------------------------------------------
#define KS_OFF 0
#define VS_OFF 4352          /* 64*68 */
#define PS_OFF 8960          /* + 64*72 */
#define SMEM_WORDS 13312     /* + 4*16*68 */

__global__ __launch_bounds__(128, 3) void attn_mma_kernel(
        const float* __restrict__ mask, float* __restrict__ out) {
    extern __shared__ __align__(16) uint32_t sm[];
    uint32_t* Ks = sm + KS_OFF;
    uint32_t* Vs = sm + VS_OFF;
    uint32_t* Ps = sm + PS_OFF;

    int tid = threadIdx.x;
    int lane = tid & 31, w = tid >> 5;       // 4 warps
    int gi = lane >> 2, ci = lane & 3;
    int qt = blockIdx.x, h = blockIdx.y, b = blockIdx.z;
    int bh = b * NH + h;
    int q0 = qt * 64;

    int row = tid >> 1, hf = tid & 1;        // staging: 64 rows x 2 halves

    // ---- stage Q (scaled 1/8, tf32) into Ps region, then build A-fragments
    {
        const float4* Qg = reinterpret_cast<const float4*>(
            g_Q + ((size_t)bh * NS + q0 + row) * ND);
        uint32_t* dst = Ps + row * 68;
#pragma unroll
        for (int j = 0; j < 8; j++) {
            float4 v = Qg[hf * 8 + j];
            v.x *= 0.125f; v.y *= 0.125f; v.z *= 0.125f; v.w *= 0.125f;
            *reinterpret_cast<uint4*>(dst + (hf * 8 + j) * 4) = tf4(v);
        }
    }
    __syncthreads();
    uint32_t qf[8][4];
    {
        const uint32_t* Qs = Ps + (w * 16) * 68;
#pragma unroll
        for (int kc = 0; kc < 8; kc++) {
            qf[kc][0] = Qs[gi * 68 + kc * 8 + ci];
            qf[kc][1] = Qs[(gi + 8) * 68 + kc * 8 + ci];
            qf[kc][2] = Qs[gi * 68 + kc * 8 + ci + 4];
            qf[kc][3] = Qs[(gi + 8) * 68 + kc * 8 + ci + 4];
        }
    }

    float oacc[8][4] = {};
    float m_lo = -3.0e38f, m_hi = -3.0e38f, l_lo = 0.f, l_hi = 0.f;

    int rlo = q0 + w * 16 + gi, rhi = rlo + 8;
    const float* mask_lo = mask + ((size_t)b * NS + rlo) * NS;
    const float* mask_hi = mask + ((size_t)b * NS + rhi) * NS;
    // flat dropout-element base for this thread's two rows (fits in u32: <2^27)
    uint32_t ebl = (uint32_t)(bh * NS + rlo) * NS + 2 * ci;
    uint32_t ebh = (uint32_t)(bh * NS + rhi) * NS + 2 * ci;

    const float* Kbase = g_K + ((size_t)bh * NS + row) * ND;
    const float* Vbase = g_V + ((size_t)bh * NS + row) * ND;

    for (int kt = 0; kt < 32; kt++) {
        // ---- load K, V tile direct (convert tf32, store to smem) ----
        {
            const float4* Kg = reinterpret_cast<const float4*>(
                Kbase + (size_t)kt * 64 * ND) + hf * 8;
            float4 t[8];
#pragma unroll
            for (int j = 0; j < 8; j++) t[j] = Kg[j];
#pragma unroll
            for (int j = 0; j < 8; j++)
                *reinterpret_cast<uint4*>(Ks + row * 68 + (hf * 8 + j) * 4) = tf4(t[j]);
            const float4* Vg = reinterpret_cast<const float4*>(
                Vbase + (size_t)kt * 64 * ND) + hf * 8;
#pragma unroll
            for (int j = 0; j < 8; j++) t[j] = Vg[j];
#pragma unroll
            for (int j = 0; j < 8; j++)
                *reinterpret_cast<uint4*>(Vs + row * 72 + (hf * 8 + j) * 4) = tf4(t[j]);
        }
        __syncthreads();

        // ---- fused threefry dropout: 32 keep bits for this thread's tile cols
        uint32_t klo = 0u, khi = 0u;
        {
            uint32_t e0 = ebl + (uint32_t)kt * 64;
            uint32_t e1 = ebh + (uint32_t)kt * 64;
#pragma unroll 2
            for (int nt = 0; nt < 8; nt++) {
                klo |= keep1(e0 + nt * 8)     << (2 * nt);
                klo |= keep1(e0 + nt * 8 + 1) << (2 * nt + 1);
                khi |= keep1(e1 + nt * 8)     << (2 * nt);
                khi |= keep1(e1 + nt * 8 + 1) << (2 * nt + 1);
            }
        }

        // ---- S = Q @ K^T ----
        float s[8][4] = {};
#pragma unroll
        for (int kc = 0; kc < 8; kc++) {
#pragma unroll
            for (int nt = 0; nt < 8; nt++) {
                uint32_t b0 = Ks[(nt * 8 + gi) * 68 + kc * 8 + ci];
                uint32_t b1 = Ks[(nt * 8 + gi) * 68 + kc * 8 + ci + 4];
                mma8(s[nt], qf[kc], b0, b1);
            }
        }

        // ---- mask + online softmax ----
        float mxl = -3.0e38f, mxh = -3.0e38f;
#pragma unroll
        for (int nt = 0; nt < 8; nt++) {
            float2 ml = *reinterpret_cast<const float2*>(
                mask_lo + kt * 64 + nt * 8 + 2 * ci);
            float2 mh = *reinterpret_cast<const float2*>(
                mask_hi + kt * 64 + nt * 8 + 2 * ci);
            s[nt][0] += ml.x; s[nt][1] += ml.y;
            s[nt][2] += mh.x; s[nt][3] += mh.y;
            mxl = fmaxf(mxl, fmaxf(s[nt][0], s[nt][1]));
            mxh = fmaxf(mxh, fmaxf(s[nt][2], s[nt][3]));
        }
        mxl = fmaxf(mxl, __shfl_xor_sync(0xffffffffu, mxl, 1));
        mxl = fmaxf(mxl, __shfl_xor_sync(0xffffffffu, mxl, 2));
        mxh = fmaxf(mxh, __shfl_xor_sync(0xffffffffu, mxh, 1));
        mxh = fmaxf(mxh, __shfl_xor_sync(0xffffffffu, mxh, 2));

        float nml = fmaxf(m_lo, mxl), nmh = fmaxf(m_hi, mxh);
        float scl = __expf(m_lo - nml), sch = __expf(m_hi - nmh);
        m_lo = nml; m_hi = nmh;

        float suml = 0.f, sumh = 0.f;
#pragma unroll
        for (int nt = 0; nt < 8; nt++) {
            s[nt][0] = __expf(s[nt][0] - nml);
            s[nt][1] = __expf(s[nt][1] - nml);
            s[nt][2] = __expf(s[nt][2] - nmh);
            s[nt][3] = __expf(s[nt][3] - nmh);
            suml += s[nt][0] + s[nt][1];
            sumh += s[nt][2] + s[nt][3];
        }
        suml += __shfl_xor_sync(0xffffffffu, suml, 1);
        suml += __shfl_xor_sync(0xffffffffu, suml, 2);
        sumh += __shfl_xor_sync(0xffffffffu, sumh, 1);
        sumh += __shfl_xor_sync(0xffffffffu, sumh, 2);
        l_lo = l_lo * scl + suml;
        l_hi = l_hi * sch + sumh;
#pragma unroll
        for (int nt = 0; nt < 8; nt++) {
            oacc[nt][0] *= scl; oacc[nt][1] *= scl;
            oacc[nt][2] *= sch; oacc[nt][3] *= sch;
        }

        // ---- dropout apply + P store (per-warp private region) ----
        uint32_t* Pw = Ps + w * 16 * 68;
#pragma unroll
        for (int nt = 0; nt < 8; nt++) {
            int c0 = nt * 8 + 2 * ci;
            uint2 plo, phi;
            plo.x = ((klo >> (2 * nt)) & 1u)     ? f2tf32(s[nt][0]) : 0u;
            plo.y = ((klo >> (2 * nt + 1)) & 1u) ? f2tf32(s[nt][1]) : 0u;
            phi.x = ((khi >> (2 * nt)) & 1u)     ? f2tf32(s[nt][2]) : 0u;
            phi.y = ((khi >> (2 * nt + 1)) & 1u) ? f2tf32(s[nt][3]) : 0u;
            *reinterpret_cast<uint2*>(Pw + gi * 68 + c0) = plo;
            *reinterpret_cast<uint2*>(Pw + (gi + 8) * 68 + c0) = phi;
        }
        __syncwarp();

        // ---- O += P @ V ----
#pragma unroll
        for (int kc = 0; kc < 8; kc++) {
            uint32_t a[4];
            a[0] = Pw[gi * 68 + kc * 8 + ci];
            a[1] = Pw[(gi + 8) * 68 + kc * 8 + ci];
            a[2] = Pw[gi * 68 + kc * 8 + ci + 4];
            a[3] = Pw[(gi + 8) * 68 + kc * 8 + ci + 4];
#pragma unroll
            for (int nt = 0; nt < 8; nt++) {
                uint32_t b0 = Vs[(kc * 8 + ci) * 72 + nt * 8 + gi];
                uint32_t b1 = Vs[(kc * 8 + ci + 4) * 72 + nt * 8 + gi];
                mma8(oacc[nt], a, b0, b1);
            }
        }
        __syncthreads();
    }

    // epilogue: out = oacc / (l * 0.9)
    float invl = 1.0f / (l_lo * 0.9f);
    float invh = 1.0f / (l_hi * 0.9f);
    float* out_lo = out + ((size_t)bh * NS + rlo) * ND;
    float* out_hi = out + ((size_t)bh * NS + rhi) * ND;
#pragma unroll
    for (int nt = 0; nt < 8; nt++) {
        float2 a, c;
        a.x = oacc[nt][0] * invl; a.y = oacc[nt][1] * invl;
        c.x = oacc[nt][2] * invh; c.y = oacc[nt][3] * invh;
        *reinterpret_cast<float2*>(out_lo + nt * 8 + 2 * ci) = a;
        *reinterpret_cast<float2*>(out_hi + nt * 8 + 2 * ci) = c;
    }
}

// ---------------------------------------------------------------------------
extern "C" void kernel_launch(void* const* d_in, const int* in_sizes, int n_in,
                              void* d_out, int out_size) {
    (void)in_sizes; (void)n_in; (void)out_size;
    const float* q   = (const float*)d_in[0];
    const float* k   = (const float*)d_in[1];
    const float* v   = (const float*)d_in[2];
    const float* msk = (const float*)d_in[3];
    const float* Wq  = (const float*)d_in[4];
    const float* bq  = (const float*)d_in[5];
    const float* Wk  = (const float*)d_in[6];
    const float* bk  = (const float*)d_in[7];
    const float* Wv  = (const float*)d_in[8];
    const float* bv  = (const float*)d_in[9];
    float* out = (float*)d_out;

    const int smem_bytes = SMEM_WORDS * 4;   // 53248 B
    cudaFuncSetAttribute(attn_mma_kernel,
                         cudaFuncAttributeMaxDynamicSharedMemorySize, smem_bytes);

    proj_kernel<<<1024, 256>>>(q, Wq, bq, 0);
    proj_kernel<<<1024, 256>>>(k, Wk, bk, 1);
    proj_kernel<<<1024, 256>>>(v, Wv, bv, 2);

    dim3 grid(NS / 64, NH, NB);
    attn_mma_kernel<<<grid, 128, smem_bytes>>>(msk, out);
}